// round 4
// baseline (speedup 1.0000x reference)
#include <cuda_runtime.h>
#include <float.h>
#include <math.h>

// Problem geometry
#define HH 512
#define WW 512
#define SLICES 128                 // B*P = 64*2
#define NB 32                      // blocks per slice
#define TPB 256                    // threads per block
#define NBLOCKS (SLICES*NB)        // 4096
#define ELEMS_PER_SLICE (HH*WW)    // 262144
#define ELEMS_PER_BLOCK (ELEMS_PER_SLICE/NB)   // 8192
#define VEC4_PER_BLOCK  (ELEMS_PER_BLOCK/4)    // 2048
#define VEC4_PER_THREAD (VEC4_PER_BLOCK/TPB)   // 8

// Per-block partials (static device scratch; no allocation)
__device__ float g_s [NBLOCKS];
__device__ float g_sx[NBLOCKS];
__device__ float g_sy[NBLOCKS];
__device__ float g_tv[NBLOCKS];
__device__ int   g_ti[NBLOCKS];

__global__ __launch_bounds__(TPB)
void dsnt_pass1(const float4* __restrict__ inp, const float4* __restrict__ tgt)
{
    const int blk   = blockIdx.x;          // 0..NBLOCKS-1
    const int slice = blk >> 5;            // /NB
    const int sub   = blk & (NB-1);
    const int tid   = threadIdx.x;

    const int slice_base4 = slice * (ELEMS_PER_SLICE/4);
    const int chunk_base4 = sub * VEC4_PER_BLOCK;

    float s = 0.f, sx = 0.f, sy = 0.f;
    float tv = -FLT_MAX;
    int   ti = 0x7fffffff;

#pragma unroll
    for (int k = 0; k < VEC4_PER_THREAD; k++) {
        const int local4 = k * TPB + tid;               // block-stride, coalesced
        const int g4     = slice_base4 + chunk_base4 + local4;
        const float4 v = inp[g4];
        const float4 t = tgt[g4];

        const int ei  = (chunk_base4 + local4) << 2;    // element index in slice
        const int row = ei >> 9;                        // /512
        const int col = ei & 511;

        const float e0 = __expf(v.x);
        const float e1 = __expf(v.y);
        const float e2 = __expf(v.z);
        const float e3 = __expf(v.w);
        const float es = (e0 + e1) + (e2 + e3);
        s  += es;
        sx += e0*(float)(col+1) + e1*(float)(col+2)
            + e2*(float)(col+3) + e3*(float)(col+4);
        sy += es * (float)(row+1);

        // target running argmax (indices visited in increasing order per thread)
        if (t.x > tv) { tv = t.x; ti = ei;     }
        if (t.y > tv) { tv = t.y; ti = ei + 1; }
        if (t.z > tv) { tv = t.z; ti = ei + 2; }
        if (t.w > tv) { tv = t.w; ti = ei + 3; }
    }

    // ---- warp reduce ----
#pragma unroll
    for (int off = 16; off > 0; off >>= 1) {
        s  += __shfl_down_sync(0xffffffffu, s,  off);
        sx += __shfl_down_sync(0xffffffffu, sx, off);
        sy += __shfl_down_sync(0xffffffffu, sy, off);
        float ov = __shfl_down_sync(0xffffffffu, tv, off);
        int   oi = __shfl_down_sync(0xffffffffu, ti, off);
        if (ov > tv || (ov == tv && oi < ti)) { tv = ov; ti = oi; }
    }

    __shared__ float sh_s[8], sh_sx[8], sh_sy[8], sh_tv[8];
    __shared__ int   sh_ti[8];
    const int wid = tid >> 5;
    const int lid = tid & 31;
    if (lid == 0) { sh_s[wid]=s; sh_sx[wid]=sx; sh_sy[wid]=sy; sh_tv[wid]=tv; sh_ti[wid]=ti; }
    __syncthreads();

    if (wid == 0) {
        s  = (lid < 8) ? sh_s [lid] : 0.f;
        sx = (lid < 8) ? sh_sx[lid] : 0.f;
        sy = (lid < 8) ? sh_sy[lid] : 0.f;
        tv = (lid < 8) ? sh_tv[lid] : -FLT_MAX;
        ti = (lid < 8) ? sh_ti[lid] : 0x7fffffff;
#pragma unroll
        for (int off = 4; off > 0; off >>= 1) {
            s  += __shfl_down_sync(0xffffffffu, s,  off);
            sx += __shfl_down_sync(0xffffffffu, sx, off);
            sy += __shfl_down_sync(0xffffffffu, sy, off);
            float ov = __shfl_down_sync(0xffffffffu, tv, off);
            int   oi = __shfl_down_sync(0xffffffffu, ti, off);
            if (ov > tv || (ov == tv && oi < ti)) { tv = ov; ti = oi; }
        }
        if (lid == 0) {
            g_s [blk] = s;
            g_sx[blk] = sx;
            g_sy[blk] = sy;
            g_tv[blk] = tv;
            g_ti[blk] = ti;
        }
    }
}

__global__ __launch_bounds__(TPB)
void dsnt_pass2(float* __restrict__ out)
{
    const int tid = threadIdx.x;
    const int wid = tid >> 5;
    const int lid = tid & 31;

    __shared__ float sh_px[SLICES], sh_py[SLICES], sh_tx[SLICES], sh_ty[SLICES];
    __shared__ double sh_red[64];

    // One warp per slice, 16 slices per warp (8 warps). Lane l reads partial l
    // of slice sl -> one coalesced 128B line per array.
#pragma unroll
    for (int it = 0; it < SLICES / 8; it++) {
        const int sl = it * 8 + wid;
        const int id = sl * NB + lid;
        double S  = (double)g_s [id];
        double SX = (double)g_sx[id];
        double SY = (double)g_sy[id];
        float  mv = g_tv[id];
        int    mi = g_ti[id];
#pragma unroll
        for (int off = 16; off > 0; off >>= 1) {
            S  += __shfl_down_sync(0xffffffffu, S,  off);
            SX += __shfl_down_sync(0xffffffffu, SX, off);
            SY += __shfl_down_sync(0xffffffffu, SY, off);
            float ov = __shfl_down_sync(0xffffffffu, mv, off);
            int   oi = __shfl_down_sync(0xffffffffu, mi, off);
            if (ov > mv || (ov == mv && oi < mi)) { mv = ov; mi = oi; }
        }
        if (lid == 0) {
            sh_px[sl] = (float)(SX / (S * 512.0));
            sh_py[sl] = (float)(SY / (S * 512.0));
            sh_tx[sl] = (float)((mi & 511) + 1) * (1.0f / 512.0f);
            sh_ty[sl] = (float)((mi >> 9)  + 1) * (1.0f / 512.0f);
        }
    }
    __syncthreads();

    if (tid < 64) {
        const int p0 = 2 * tid, p1 = 2 * tid + 1;
        const double px0 = sh_px[p0], py0 = sh_py[p0];
        const double px1 = sh_px[p1], py1 = sh_py[p1];
        const double tx0 = sh_tx[p0], ty0 = sh_ty[p0];
        const double tx1 = sh_tx[p1], ty1 = sh_ty[p1];

        const double dx0 = tx0 - px0, dy0 = ty0 - py0;
        const double dx1 = tx1 - px1, dy1 = ty1 - py1;
        const double ed  = sqrt(dx0*dx0 + dy0*dy0) + sqrt(dx1*dx1 + dy1*dy1);

        const double pvx = px0 - px1, pvy = py0 - py1;
        const double tvx = tx0 - tx1, tvy = ty0 - ty1;
        const double pd  = sqrt(pvx*pvx + pvy*pvy);
        const double td  = sqrt(tvx*tvx + tvy*tvy);
        const double dot = pvx*tvx + pvy*tvy;

        sh_red[tid] = ed + fabs(pd - td) + (1.0 - cos(dot / (pd * td)));
    }
    __syncthreads();

    if (tid == 0) {
        double acc = 0.0;
#pragma unroll
        for (int i = 0; i < 64; i++) acc += sh_red[i];
        out[0] = (float)(acc / 64.0);
    }
}

extern "C" void kernel_launch(void* const* d_in, const int* in_sizes, int n_in,
                              void* d_out, int out_size)
{
    const float4* inp = (const float4*)d_in[0];
    const float4* tgt = (const float4*)d_in[1];
    float* out = (float*)d_out;

    dsnt_pass1<<<NBLOCKS, TPB>>>(inp, tgt);
    dsnt_pass2<<<1, TPB>>>(out);
}

// round 8
// speedup vs baseline: 1.7154x; 1.7154x over previous
#include <cuda_runtime.h>
#include <float.h>
#include <math.h>

// Problem geometry
#define HH 512
#define WW 512
#define SLICES 128                 // B*P = 64*2
#define NB 32                      // blocks per slice
#define TPB 256                    // threads per block
#define NBLOCKS (SLICES*NB)        // 4096
#define ELEMS_PER_SLICE (HH*WW)    // 262144
#define ELEMS_PER_BLOCK (ELEMS_PER_SLICE/NB)   // 8192
#define VEC4_PER_BLOCK  (ELEMS_PER_BLOCK/4)    // 2048
#define VEC4_PER_THREAD (VEC4_PER_BLOCK/TPB)   // 8

// Per-block partials (static device scratch; no allocation)
__device__ float g_s [NBLOCKS];
__device__ float g_sx[NBLOCKS];
__device__ float g_sy[NBLOCKS];
__device__ float g_tv[NBLOCKS];
__device__ int   g_ti[NBLOCKS];

__global__ __launch_bounds__(TPB)
void dsnt_pass1(const float4* __restrict__ inp, const float4* __restrict__ tgt)
{
    const int blk   = blockIdx.x;          // 0..NBLOCKS-1
    const int slice = blk >> 5;            // /NB
    const int sub   = blk & (NB-1);
    const int tid   = threadIdx.x;

    const int slice_base4 = slice * (ELEMS_PER_SLICE/4);
    const int chunk_base4 = sub * VEC4_PER_BLOCK;

    float s = 0.f, sx = 0.f, sy = 0.f;
    float tv = -FLT_MAX;
    int   ti = 0x7fffffff;

#pragma unroll
    for (int k = 0; k < VEC4_PER_THREAD; k++) {
        const int local4 = k * TPB + tid;               // block-stride, coalesced
        const int g4     = slice_base4 + chunk_base4 + local4;
        const float4 v = inp[g4];
        const float4 t = tgt[g4];

        const int ei  = (chunk_base4 + local4) << 2;    // element index in slice
        const int row = ei >> 9;                        // /512
        const int col = ei & 511;

        const float e0 = __expf(v.x);
        const float e1 = __expf(v.y);
        const float e2 = __expf(v.z);
        const float e3 = __expf(v.w);
        const float es = (e0 + e1) + (e2 + e3);
        s  += es;
        sx += e0*(float)(col+1) + e1*(float)(col+2)
            + e2*(float)(col+3) + e3*(float)(col+4);
        sy += es * (float)(row+1);

        // target running argmax (indices visited in increasing order per thread)
        if (t.x > tv) { tv = t.x; ti = ei;     }
        if (t.y > tv) { tv = t.y; ti = ei + 1; }
        if (t.z > tv) { tv = t.z; ti = ei + 2; }
        if (t.w > tv) { tv = t.w; ti = ei + 3; }
    }

    // ---- warp reduce ----
#pragma unroll
    for (int off = 16; off > 0; off >>= 1) {
        s  += __shfl_down_sync(0xffffffffu, s,  off);
        sx += __shfl_down_sync(0xffffffffu, sx, off);
        sy += __shfl_down_sync(0xffffffffu, sy, off);
        float ov = __shfl_down_sync(0xffffffffu, tv, off);
        int   oi = __shfl_down_sync(0xffffffffu, ti, off);
        if (ov > tv || (ov == tv && oi < ti)) { tv = ov; ti = oi; }
    }

    __shared__ float sh_s[8], sh_sx[8], sh_sy[8], sh_tv[8];
    __shared__ int   sh_ti[8];
    const int wid = tid >> 5;
    const int lid = tid & 31;
    if (lid == 0) { sh_s[wid]=s; sh_sx[wid]=sx; sh_sy[wid]=sy; sh_tv[wid]=tv; sh_ti[wid]=ti; }
    __syncthreads();

    if (wid == 0) {
        s  = (lid < 8) ? sh_s [lid] : 0.f;
        sx = (lid < 8) ? sh_sx[lid] : 0.f;
        sy = (lid < 8) ? sh_sy[lid] : 0.f;
        tv = (lid < 8) ? sh_tv[lid] : -FLT_MAX;
        ti = (lid < 8) ? sh_ti[lid] : 0x7fffffff;
#pragma unroll
        for (int off = 4; off > 0; off >>= 1) {
            s  += __shfl_down_sync(0xffffffffu, s,  off);
            sx += __shfl_down_sync(0xffffffffu, sx, off);
            sy += __shfl_down_sync(0xffffffffu, sy, off);
            float ov = __shfl_down_sync(0xffffffffu, tv, off);
            int   oi = __shfl_down_sync(0xffffffffu, ti, off);
            if (ov > tv || (ov == tv && oi < ti)) { tv = ov; ti = oi; }
        }
        if (lid == 0) {
            g_s [blk] = s;
            g_sx[blk] = sx;
            g_sy[blk] = sy;
            g_tv[blk] = tv;
            g_ti[blk] = ti;
        }
    }
}

__global__ __launch_bounds__(TPB)
void dsnt_pass2(float* __restrict__ out)
{
    const int tid = threadIdx.x;
    const int wid = tid >> 5;
    const int lid = tid & 31;

    __shared__ float sh_px[SLICES], sh_py[SLICES], sh_tx[SLICES], sh_ty[SLICES];
    __shared__ float sh_red[64];

    // One warp per slice, 16 slices per warp (8 warps). Lane l reads partial l
    // of slice sl -> one coalesced 128B line per array. All fp32 (fp64 pipe on
    // sm_103a is ~18.4 cyc/op/SM — avoid entirely).
#pragma unroll
    for (int it = 0; it < SLICES / 8; it++) {
        const int sl = it * 8 + wid;
        const int id = sl * NB + lid;
        float S  = g_s [id];
        float SX = g_sx[id];
        float SY = g_sy[id];
        float mv = g_tv[id];
        int   mi = g_ti[id];
#pragma unroll
        for (int off = 16; off > 0; off >>= 1) {
            S  += __shfl_down_sync(0xffffffffu, S,  off);
            SX += __shfl_down_sync(0xffffffffu, SX, off);
            SY += __shfl_down_sync(0xffffffffu, SY, off);
            float ov = __shfl_down_sync(0xffffffffu, mv, off);
            int   oi = __shfl_down_sync(0xffffffffu, mi, off);
            if (ov > mv || (ov == mv && oi < mi)) { mv = ov; mi = oi; }
        }
        if (lid == 0) {
            const float inv = 1.0f / (S * 512.0f);
            sh_px[sl] = SX * inv;
            sh_py[sl] = SY * inv;
            sh_tx[sl] = (float)((mi & 511) + 1) * (1.0f / 512.0f);
            sh_ty[sl] = (float)((mi >> 9)  + 1) * (1.0f / 512.0f);
        }
    }
    __syncthreads();

    if (tid < 64) {
        const int p0 = 2 * tid, p1 = 2 * tid + 1;
        const float px0 = sh_px[p0], py0 = sh_py[p0];
        const float px1 = sh_px[p1], py1 = sh_py[p1];
        const float tx0 = sh_tx[p0], ty0 = sh_ty[p0];
        const float tx1 = sh_tx[p1], ty1 = sh_ty[p1];

        const float dx0 = tx0 - px0, dy0 = ty0 - py0;
        const float dx1 = tx1 - px1, dy1 = ty1 - py1;
        const float ed  = sqrtf(dx0*dx0 + dy0*dy0) + sqrtf(dx1*dx1 + dy1*dy1);

        const float pvx = px0 - px1, pvy = py0 - py1;
        const float tvx = tx0 - tx1, tvy = ty0 - ty1;
        const float pd  = sqrtf(pvx*pvx + pvy*pvy);
        const float td  = sqrtf(tvx*tvx + tvy*tvy);
        const float dot = pvx*tvx + pvy*tvy;

        sh_red[tid] = ed + fabsf(pd - td) + (1.0f - cosf(dot / (pd * td)));
    }
    __syncthreads();

    // pairwise tree sum of the 64 per-batch terms (fp32, deterministic)
    if (tid < 32) {
        float a = sh_red[tid] + sh_red[tid + 32];
#pragma unroll
        for (int off = 16; off > 0; off >>= 1)
            a += __shfl_down_sync(0xffffffffu, a, off);
        if (tid == 0) out[0] = a * (1.0f / 64.0f);
    }
}

extern "C" void kernel_launch(void* const* d_in, const int* in_sizes, int n_in,
                              void* d_out, int out_size)
{
    const float4* inp = (const float4*)d_in[0];
    const float4* tgt = (const float4*)d_in[1];
    float* out = (float*)d_out;

    dsnt_pass1<<<NBLOCKS, TPB>>>(inp, tgt);
    dsnt_pass2<<<1, TPB>>>(out);
}

// round 9
// speedup vs baseline: 1.7557x; 1.0235x over previous
#include <cuda_runtime.h>
#include <float.h>
#include <math.h>

// Problem geometry
#define HH 512
#define WW 512
#define SLICES 128                 // B*P = 64*2
#define NB 32                      // blocks per slice
#define TPB 256                    // threads per block
#define NBLOCKS (SLICES*NB)        // 4096
#define ELEMS_PER_SLICE (HH*WW)    // 262144
#define ELEMS_PER_BLOCK (ELEMS_PER_SLICE/NB)   // 8192
#define VEC4_PER_BLOCK  (ELEMS_PER_BLOCK/4)    // 2048
#define VEC4_PER_THREAD (VEC4_PER_BLOCK/TPB)   // 8

// Per-block partials (static device scratch; no allocation)
__device__ float g_s [NBLOCKS];
__device__ float g_sx[NBLOCKS];
__device__ float g_sy[NBLOCKS];
__device__ float g_tv[NBLOCKS];
__device__ int   g_ti[NBLOCKS];

__global__ __launch_bounds__(TPB)
void dsnt_pass1(const float4* __restrict__ inp, const float4* __restrict__ tgt)
{
    const int blk   = blockIdx.x;          // 0..NBLOCKS-1
    const int slice = blk >> 5;            // /NB
    const int sub   = blk & (NB-1);
    const int tid   = threadIdx.x;

    const int slice_base4 = slice * (ELEMS_PER_SLICE/4);
    const int chunk_base4 = sub * VEC4_PER_BLOCK;

    float s = 0.f, sx = 0.f, sy = 0.f;
    float tv = -FLT_MAX;
    int   ti = 0x7fffffff;

#pragma unroll
    for (int k = 0; k < VEC4_PER_THREAD; k++) {
        const int local4 = k * TPB + tid;               // block-stride, coalesced
        const int g4     = slice_base4 + chunk_base4 + local4;
        const float4 v = inp[g4];
        const float4 t = tgt[g4];

        const int ei  = (chunk_base4 + local4) << 2;    // element index in slice
        const int row = ei >> 9;                        // /512
        const int col = ei & 511;

        const float e0 = __expf(v.x);
        const float e1 = __expf(v.y);
        const float e2 = __expf(v.z);
        const float e3 = __expf(v.w);
        const float es = (e0 + e1) + (e2 + e3);
        s  += es;
        sx += e0*(float)(col+1) + e1*(float)(col+2)
            + e2*(float)(col+3) + e3*(float)(col+4);
        sy += es * (float)(row+1);

        // target running argmax (indices visited in increasing order per thread)
        if (t.x > tv) { tv = t.x; ti = ei;     }
        if (t.y > tv) { tv = t.y; ti = ei + 1; }
        if (t.z > tv) { tv = t.z; ti = ei + 2; }
        if (t.w > tv) { tv = t.w; ti = ei + 3; }
    }

    // ---- warp reduce ----
#pragma unroll
    for (int off = 16; off > 0; off >>= 1) {
        s  += __shfl_down_sync(0xffffffffu, s,  off);
        sx += __shfl_down_sync(0xffffffffu, sx, off);
        sy += __shfl_down_sync(0xffffffffu, sy, off);
        float ov = __shfl_down_sync(0xffffffffu, tv, off);
        int   oi = __shfl_down_sync(0xffffffffu, ti, off);
        if (ov > tv || (ov == tv && oi < ti)) { tv = ov; ti = oi; }
    }

    __shared__ float sh_s[8], sh_sx[8], sh_sy[8], sh_tv[8];
    __shared__ int   sh_ti[8];
    const int wid = tid >> 5;
    const int lid = tid & 31;
    if (lid == 0) { sh_s[wid]=s; sh_sx[wid]=sx; sh_sy[wid]=sy; sh_tv[wid]=tv; sh_ti[wid]=ti; }
    __syncthreads();

    if (wid == 0) {
        s  = (lid < 8) ? sh_s [lid] : 0.f;
        sx = (lid < 8) ? sh_sx[lid] : 0.f;
        sy = (lid < 8) ? sh_sy[lid] : 0.f;
        tv = (lid < 8) ? sh_tv[lid] : -FLT_MAX;
        ti = (lid < 8) ? sh_ti[lid] : 0x7fffffff;
#pragma unroll
        for (int off = 4; off > 0; off >>= 1) {
            s  += __shfl_down_sync(0xffffffffu, s,  off);
            sx += __shfl_down_sync(0xffffffffu, sx, off);
            sy += __shfl_down_sync(0xffffffffu, sy, off);
            float ov = __shfl_down_sync(0xffffffffu, tv, off);
            int   oi = __shfl_down_sync(0xffffffffu, ti, off);
            if (ov > tv || (ov == tv && oi < ti)) { tv = ov; ti = oi; }
        }
        if (lid == 0) {
            g_s [blk] = s;
            g_sx[blk] = sx;
            g_sy[blk] = sy;
            g_tv[blk] = tv;
            g_ti[blk] = ti;
        }
    }
}

__global__ __launch_bounds__(128)
void dsnt_pass2(float* __restrict__ out)
{
    const int t = threadIdx.x;   // 0..127: one thread per slice

    __shared__ float sh_px[SLICES], sh_py[SLICES], sh_tx[SLICES], sh_ty[SLICES];
    __shared__ float sh_red[64];

    // One thread per slice: its 32 partials are 32 consecutive floats (one
    // 128B line per array) -> first load fetches the line, rest hit L1.
    // Serial fp32 adds: FADD lat 4 x 32 = ~128 cyc per chain, 3 chains of ILP.
    {
        float S = 0.f, SX = 0.f, SY = 0.f;
        float mv = -FLT_MAX;
        int   mi = 0x7fffffff;
#pragma unroll
        for (int j = 0; j < NB; j++) {
            const int id = t * NB + j;
            S  += g_s [id];
            SX += g_sx[id];
            SY += g_sy[id];
            const float v = g_tv[id];
            const int   i = g_ti[id];
            // partials are in increasing index-range order; '>' keeps the
            // first (smallest-index) maximum — matches argmax semantics.
            if (v > mv) { mv = v; mi = i; }
        }
        const float inv = 1.0f / (S * 512.0f);
        sh_px[t] = SX * inv;
        sh_py[t] = SY * inv;
        sh_tx[t] = (float)((mi & 511) + 1) * (1.0f / 512.0f);
        sh_ty[t] = (float)((mi >> 9)  + 1) * (1.0f / 512.0f);
    }
    __syncthreads();

    if (t < 64) {
        const int p0 = 2 * t, p1 = 2 * t + 1;
        const float px0 = sh_px[p0], py0 = sh_py[p0];
        const float px1 = sh_px[p1], py1 = sh_py[p1];
        const float tx0 = sh_tx[p0], ty0 = sh_ty[p0];
        const float tx1 = sh_tx[p1], ty1 = sh_ty[p1];

        const float dx0 = tx0 - px0, dy0 = ty0 - py0;
        const float dx1 = tx1 - px1, dy1 = ty1 - py1;
        const float ed  = sqrtf(dx0*dx0 + dy0*dy0) + sqrtf(dx1*dx1 + dy1*dy1);

        const float pvx = px0 - px1, pvy = py0 - py1;
        const float tvx = tx0 - tx1, tvy = ty0 - ty1;
        const float pd  = sqrtf(pvx*pvx + pvy*pvy);
        const float td  = sqrtf(tvx*tvx + tvy*tvy);
        const float dot = pvx*tvx + pvy*tvy;

        sh_red[t] = ed + fabsf(pd - td) + (1.0f - cosf(dot / (pd * td)));
    }
    __syncthreads();

    // pairwise tree sum of the 64 per-batch terms (fp32, deterministic)
    if (t < 32) {
        float a = sh_red[t] + sh_red[t + 32];
#pragma unroll
        for (int off = 16; off > 0; off >>= 1)
            a += __shfl_down_sync(0xffffffffu, a, off);
        if (t == 0) out[0] = a * (1.0f / 64.0f);
    }
}

extern "C" void kernel_launch(void* const* d_in, const int* in_sizes, int n_in,
                              void* d_out, int out_size)
{
    const float4* inp = (const float4*)d_in[0];
    const float4* tgt = (const float4*)d_in[1];
    float* out = (float*)d_out;

    dsnt_pass1<<<NBLOCKS, TPB>>>(inp, tgt);
    dsnt_pass2<<<1, 128>>>(out);
}

// round 11
// speedup vs baseline: 2.0468x; 1.1658x over previous
#include <cuda_runtime.h>
#include <float.h>
#include <math.h>

// Problem geometry
#define HH 512
#define WW 512
#define SLICES 128                 // B*P = 64*2
#define NB 32                      // blocks per slice
#define TPB 256                    // threads per block
#define NBLOCKS (SLICES*NB)        // 4096
#define ELEMS_PER_SLICE (HH*WW)    // 262144
#define ELEMS_PER_BLOCK (ELEMS_PER_SLICE/NB)   // 8192
#define VEC4_PER_BLOCK  (ELEMS_PER_BLOCK/4)    // 2048
#define VEC4_PER_THREAD (VEC4_PER_BLOCK/TPB)   // 8

// Per-block partials (static device scratch; 16B-aligned for float4 loads)
__device__ __align__(16) float g_s [NBLOCKS];
__device__ __align__(16) float g_sx[NBLOCKS];
__device__ __align__(16) float g_sy[NBLOCKS];
__device__ __align__(16) float g_tv[NBLOCKS];
__device__ __align__(16) int   g_ti[NBLOCKS];

__global__ __launch_bounds__(TPB)
void dsnt_pass1(const float4* __restrict__ inp, const float4* __restrict__ tgt)
{
    const int blk   = blockIdx.x;          // 0..NBLOCKS-1
    const int slice = blk >> 5;            // /NB
    const int sub   = blk & (NB-1);
    const int tid   = threadIdx.x;

    const int slice_base4 = slice * (ELEMS_PER_SLICE/4);
    const int chunk_base4 = sub * VEC4_PER_BLOCK;

    float s = 0.f, sx = 0.f, sy = 0.f;
    float tv = -FLT_MAX;
    int   ti = 0x7fffffff;

#pragma unroll
    for (int k = 0; k < VEC4_PER_THREAD; k++) {
        const int local4 = k * TPB + tid;               // block-stride, coalesced
        const int g4     = slice_base4 + chunk_base4 + local4;
        const float4 v = inp[g4];
        const float4 t = tgt[g4];

        const int ei  = (chunk_base4 + local4) << 2;    // element index in slice
        const int row = ei >> 9;                        // /512
        const int col = ei & 511;

        const float e0 = __expf(v.x);
        const float e1 = __expf(v.y);
        const float e2 = __expf(v.z);
        const float e3 = __expf(v.w);
        const float es = (e0 + e1) + (e2 + e3);
        s  += es;
        sx += e0*(float)(col+1) + e1*(float)(col+2)
            + e2*(float)(col+3) + e3*(float)(col+4);
        sy += es * (float)(row+1);

        // target running argmax (indices visited in increasing order per thread)
        if (t.x > tv) { tv = t.x; ti = ei;     }
        if (t.y > tv) { tv = t.y; ti = ei + 1; }
        if (t.z > tv) { tv = t.z; ti = ei + 2; }
        if (t.w > tv) { tv = t.w; ti = ei + 3; }
    }

    // ---- warp reduce ----
#pragma unroll
    for (int off = 16; off > 0; off >>= 1) {
        s  += __shfl_down_sync(0xffffffffu, s,  off);
        sx += __shfl_down_sync(0xffffffffu, sx, off);
        sy += __shfl_down_sync(0xffffffffu, sy, off);
        float ov = __shfl_down_sync(0xffffffffu, tv, off);
        int   oi = __shfl_down_sync(0xffffffffu, ti, off);
        if (ov > tv || (ov == tv && oi < ti)) { tv = ov; ti = oi; }
    }

    __shared__ float sh_s[8], sh_sx[8], sh_sy[8], sh_tv[8];
    __shared__ int   sh_ti[8];
    const int wid = tid >> 5;
    const int lid = tid & 31;
    if (lid == 0) { sh_s[wid]=s; sh_sx[wid]=sx; sh_sy[wid]=sy; sh_tv[wid]=tv; sh_ti[wid]=ti; }
    __syncthreads();

    if (wid == 0) {
        s  = (lid < 8) ? sh_s [lid] : 0.f;
        sx = (lid < 8) ? sh_sx[lid] : 0.f;
        sy = (lid < 8) ? sh_sy[lid] : 0.f;
        tv = (lid < 8) ? sh_tv[lid] : -FLT_MAX;
        ti = (lid < 8) ? sh_ti[lid] : 0x7fffffff;
#pragma unroll
        for (int off = 4; off > 0; off >>= 1) {
            s  += __shfl_down_sync(0xffffffffu, s,  off);
            sx += __shfl_down_sync(0xffffffffu, sx, off);
            sy += __shfl_down_sync(0xffffffffu, sy, off);
            float ov = __shfl_down_sync(0xffffffffu, tv, off);
            int   oi = __shfl_down_sync(0xffffffffu, ti, off);
            if (ov > tv || (ov == tv && oi < ti)) { tv = ov; ti = oi; }
        }
        if (lid == 0) {
            g_s [blk] = s;
            g_sx[blk] = sx;
            g_sy[blk] = sy;
            g_tv[blk] = tv;
            g_ti[blk] = ti;
        }
    }
}

// ---------------------------------------------------------------------------
// Pass 2: 512 threads, 4 threads per slice, 8 partials per thread via
// float4/int4 loads (10 independent 16B loads/thread -> MLP=10, one DRAM
// round-trip for the whole reduction instead of ~40 serialized ones).
// ---------------------------------------------------------------------------
#define TPB2 512

__global__ __launch_bounds__(TPB2)
void dsnt_pass2(float* __restrict__ out)
{
    const int t = threadIdx.x;          // 0..511
    const int sl   = t >> 2;            // slice 0..127
    const int part = t & 3;             // 0..3 (8 partials each)

    __shared__ float sS [TPB2], sSX[TPB2], sSY[TPB2], sMV[TPB2];
    __shared__ int   sMI[TPB2];
    __shared__ float sh_px[SLICES], sh_py[SLICES], sh_tx[SLICES], sh_ty[SLICES];
    __shared__ float sh_red[64];

    // ---- phase 1: each thread reduces its 8 partials (vector loads) ----
    {
        const int v4 = sl * (NB/4) + part * 2;          // float4 index
        const float4 s0  = ((const float4*)g_s )[v4];
        const float4 s1  = ((const float4*)g_s )[v4+1];
        const float4 x0  = ((const float4*)g_sx)[v4];
        const float4 x1  = ((const float4*)g_sx)[v4+1];
        const float4 y0  = ((const float4*)g_sy)[v4];
        const float4 y1  = ((const float4*)g_sy)[v4+1];
        const float4 m0  = ((const float4*)g_tv)[v4];
        const float4 m1  = ((const float4*)g_tv)[v4+1];
        const int4   i0  = ((const int4*  )g_ti)[v4];
        const int4   i1  = ((const int4*  )g_ti)[v4+1];

        sS [t] = ((s0.x + s0.y) + (s0.z + s0.w)) + ((s1.x + s1.y) + (s1.z + s1.w));
        sSX[t] = ((x0.x + x0.y) + (x0.z + x0.w)) + ((x1.x + x1.y) + (x1.z + x1.w));
        sSY[t] = ((y0.x + y0.y) + (y0.z + y0.w)) + ((y1.x + y1.y) + (y1.z + y1.w));

        // argmax over the 8 (value,index) pairs; sub-blocks are in increasing
        // index order, so strict '>' keeps the first (smallest-index) max.
        float mv = m0.x; int mi = i0.x;
        if (m0.y > mv) { mv = m0.y; mi = i0.y; }
        if (m0.z > mv) { mv = m0.z; mi = i0.z; }
        if (m0.w > mv) { mv = m0.w; mi = i0.w; }
        if (m1.x > mv) { mv = m1.x; mi = i1.x; }
        if (m1.y > mv) { mv = m1.y; mi = i1.y; }
        if (m1.z > mv) { mv = m1.z; mi = i1.z; }
        if (m1.w > mv) { mv = m1.w; mi = i1.w; }
        sMV[t] = mv;
        sMI[t] = mi;
    }
    __syncthreads();

    // ---- phase 2: combine the 4 sub-results per slice ----
    if (t < SLICES) {
        const int b = t * 4;
        float S  = ((sS [b] + sS [b+1]) + (sS [b+2] + sS [b+3]));
        float SX = ((sSX[b] + sSX[b+1]) + (sSX[b+2] + sSX[b+3]));
        float SY = ((sSY[b] + sSY[b+1]) + (sSY[b+2] + sSY[b+3]));
        float mv = sMV[b]; int mi = sMI[b];
        if (sMV[b+1] > mv) { mv = sMV[b+1]; mi = sMI[b+1]; }
        if (sMV[b+2] > mv) { mv = sMV[b+2]; mi = sMI[b+2]; }
        if (sMV[b+3] > mv) { mv = sMV[b+3]; mi = sMI[b+3]; }

        const float inv = 1.0f / (S * 512.0f);
        sh_px[t] = SX * inv;
        sh_py[t] = SY * inv;
        sh_tx[t] = (float)((mi & 511) + 1) * (1.0f / 512.0f);
        sh_ty[t] = (float)((mi >> 9)  + 1) * (1.0f / 512.0f);
    }
    __syncthreads();

    // ---- phase 3: per-batch loss terms ----
    if (t < 64) {
        const int p0 = 2 * t, p1 = 2 * t + 1;
        const float px0 = sh_px[p0], py0 = sh_py[p0];
        const float px1 = sh_px[p1], py1 = sh_py[p1];
        const float tx0 = sh_tx[p0], ty0 = sh_ty[p0];
        const float tx1 = sh_tx[p1], ty1 = sh_ty[p1];

        const float dx0 = tx0 - px0, dy0 = ty0 - py0;
        const float dx1 = tx1 - px1, dy1 = ty1 - py1;
        const float ed  = sqrtf(dx0*dx0 + dy0*dy0) + sqrtf(dx1*dx1 + dy1*dy1);

        const float pvx = px0 - px1, pvy = py0 - py1;
        const float tvx = tx0 - tx1, tvy = ty0 - ty1;
        const float pd  = sqrtf(pvx*pvx + pvy*pvy);
        const float td  = sqrtf(tvx*tvx + tvy*tvy);
        const float dot = pvx*tvx + pvy*tvy;

        sh_red[t] = ed + fabsf(pd - td) + (1.0f - cosf(dot / (pd * td)));
    }
    __syncthreads();

    // ---- phase 4: tree sum of 64 per-batch terms ----
    if (t < 32) {
        float a = sh_red[t] + sh_red[t + 32];
#pragma unroll
        for (int off = 16; off > 0; off >>= 1)
            a += __shfl_down_sync(0xffffffffu, a, off);
        if (t == 0) out[0] = a * (1.0f / 64.0f);
    }
}

extern "C" void kernel_launch(void* const* d_in, const int* in_sizes, int n_in,
                              void* d_out, int out_size)
{
    const float4* inp = (const float4*)d_in[0];
    const float4* tgt = (const float4*)d_in[1];
    float* out = (float*)d_out;

    dsnt_pass1<<<NBLOCKS, TPB>>>(inp, tgt);
    dsnt_pass2<<<1, TPB2>>>(out);
}